// round 16
// baseline (speedup 1.0000x reference)
#include <cuda_runtime.h>
#include <cuda_bf16.h>
#include <cuda_fp16.h>
#include <stdint.h>

#define NPIX 6400
#define IMGW 80
#define CIN 256
#define CK 128
#define CV 256
#define QT 64
#define KT 128
#define SQRT_LOG2E 1.2011224087864498f
// job table: 156 q-jobs x 2 splits (25 it) + 44 q-jobs x 3 splits (17/17/16 it) = 444 CTAs
#define NBIG 312
#define QSPLIT2 156

// ---------------- scratch ----------------
__device__ __half g_xT[(size_t)2 * NPIX * CIN];
__device__ __half g_Kh[(size_t)2 * NPIX * CK];   // K pre-scaled by sqrt(log2e)
__device__ __nv_bfloat16 g_V[(size_t)2 * NPIX * CV];
__device__ float g_part[(size_t)2 * 3 * NPIX * CV];
__device__ float g_l[2 * 3 * NPIX];
__device__ float g_kbias[CK];
__device__ __half g_wkh[CK * CIN];
__device__ __half g_wvh[9 * CV * CIN];
__device__ __half g_wwh[CV * CV];

// ---------------- PTX helpers ----------------
__device__ __forceinline__ uint32_t smem_u32(const void* p) {
    uint32_t a;
    asm("{ .reg .u64 t; cvta.to.shared.u64 t, %1; cvt.u32.u64 %0, t; }" : "=r"(a) : "l"(p));
    return a;
}
__device__ __forceinline__ void ldsm4(uint32_t* r, uint32_t addr) {
    asm volatile("ldmatrix.sync.aligned.m8n8.x4.shared.b16 {%0,%1,%2,%3}, [%4];"
                 : "=r"(r[0]), "=r"(r[1]), "=r"(r[2]), "=r"(r[3]) : "r"(addr));
}
__device__ __forceinline__ void ldsm4t(uint32_t* r, uint32_t addr) {
    asm volatile("ldmatrix.sync.aligned.m8n8.x4.trans.shared.b16 {%0,%1,%2,%3}, [%4];"
                 : "=r"(r[0]), "=r"(r[1]), "=r"(r[2]), "=r"(r[3]) : "r"(addr));
}
__device__ __forceinline__ void mma_bf16(float* c, const uint32_t* a, uint32_t b0, uint32_t b1) {
    asm volatile("mma.sync.aligned.m16n8k16.row.col.f32.bf16.bf16.f32 "
                 "{%0,%1,%2,%3}, {%4,%5,%6,%7}, {%8,%9}, {%0,%1,%2,%3};"
                 : "+f"(c[0]), "+f"(c[1]), "+f"(c[2]), "+f"(c[3])
                 : "r"(a[0]), "r"(a[1]), "r"(a[2]), "r"(a[3]), "r"(b0), "r"(b1));
}
__device__ __forceinline__ void mma_f16(float* c, const uint32_t* a, uint32_t b0, uint32_t b1) {
    asm volatile("mma.sync.aligned.m16n8k16.row.col.f32.f16.f16.f32 "
                 "{%0,%1,%2,%3}, {%4,%5,%6,%7}, {%8,%9}, {%0,%1,%2,%3};"
                 : "+f"(c[0]), "+f"(c[1]), "+f"(c[2]), "+f"(c[3])
                 : "r"(a[0]), "r"(a[1]), "r"(a[2]), "r"(a[3]), "r"(b0), "r"(b1));
}
__device__ __forceinline__ void cpa16(uint32_t dst, const void* src, int sz) {
    asm volatile("cp.async.cg.shared.global [%0], [%1], 16, %2;"
                 :: "r"(dst), "l"(src), "r"(sz));
}
#define CP_COMMIT() asm volatile("cp.async.commit_group;" ::: "memory")
#define CP_WAIT(n)  asm volatile("cp.async.wait_group %0;" :: "n"(n) : "memory")
__device__ __forceinline__ void bar_sync(int id, int cnt) {
    asm volatile("bar.sync %0, %1;" :: "r"(id), "r"(cnt) : "memory");
}
__device__ __forceinline__ void bar_arrive(int id, int cnt) {
    asm volatile("bar.arrive %0, %1;" :: "r"(id), "r"(cnt) : "memory");
}
__device__ __forceinline__ float ex2(float x) {
    float y;
    asm("ex2.approx.ftz.f32 %0, %1;" : "=f"(y) : "f"(x));
    return y;
}

// ---------------- x transpose + weight prep (merged; one launch) ------------------
__global__ void transpose_prep_kernel(const float* __restrict__ x,
                                      const float* __restrict__ wk, const float* __restrict__ bk,
                                      const float* __restrict__ gamma, const float* __restrict__ beta,
                                      const float* __restrict__ rmean, const float* __restrict__ rvar,
                                      const float* __restrict__ wv, const float* __restrict__ ww) {
    __shared__ float t[32][33];
    int b = blockIdx.z, n0 = blockIdx.x * 32, c0 = blockIdx.y * 32;
    int tid = threadIdx.x, nl = tid & 31, cg = tid >> 5;

    // ---- prep (independent of the transpose data; interleaved for free) ----
    int flat = ((blockIdx.z * 8 + blockIdx.y) * 200 + blockIdx.x) * 256 + tid;
    if (flat < CK) {
        float inv = gamma[flat] * rsqrtf(rvar[flat] + 1e-5f);
        g_kbias[flat] = bk[flat] * inv + beta[flat] - rmean[flat] * inv;
    }
    if (flat < CK * CIN) {
        int c = flat / CIN;
        float inv = gamma[c] * rsqrtf(rvar[c] + 1e-5f);
        g_wkh[flat] = __float2half(wk[flat] * inv);
    }
    {
        int i2 = flat - CK * CIN;
        if (i2 >= 0 && i2 < CV * CV)
            g_wwh[i2] = __float2half(ww[i2]);
    }
    {
        int i3 = flat - (CK * CIN + CV * CV);
        if (i3 >= 0 && i3 < 9 * CV * CIN) {
            int tp = i3 / (CV * CIN);
            int rem = i3 - tp * CV * CIN;
            int o = rem / CIN;
            int i = rem - o * CIN;
            g_wvh[i3] = __float2half(wv[(o * CIN + i) * 9 + tp]);
        }
    }

    // ---- transpose ----
#pragma unroll
    for (int i = 0; i < 4; i++) {
        int c = cg + i * 8;
        t[c][nl] = x[((size_t)b * CIN + c0 + c) * NPIX + n0 + nl];
    }
    __syncthreads();
    __half2 h0 = __floats2half2_rn(t[cg * 4 + 0][nl], t[cg * 4 + 1][nl]);
    __half2 h1 = __floats2half2_rn(t[cg * 4 + 2][nl], t[cg * 4 + 3][nl]);
    uint2 v;
    v.x = *(uint32_t*)&h0; v.y = *(uint32_t*)&h1;
    *(uint2*)(g_xT + ((size_t)b * NPIX + n0 + nl) * CIN + c0 + cg * 4) = v;
}

// ---------------- conv as implicit NT GEMM (fp16 mma, BM=64, BN=64, BK=128) -------
// Smaller tiles: 800 CTAs (conv9) pack the 296 concurrent-CTA slots with far less
// wave quantization than 400. Per-output accumulation order unchanged.
template <int COUT, int NTAPS>
__global__ __launch_bounds__(256, 2) void conv_mma_kernel(const float* __restrict__ bias_v) {
    extern __shared__ unsigned char smem[];
    uint32_t sb = smem_u32(smem);
    const uint32_t AB0 = sb, BB0 = sb + 32768;   // A: 2x16KB, B: 2x16KB

    int tid = threadIdx.x, lane = tid & 31, wid = tid >> 5;
    int wm = wid & 3, wn = wid >> 2;             // 4m x 2n over 64x64
    int b = blockIdx.z, m0 = blockIdx.y * 64, c0 = blockIdx.x * 64;

    const __half* xTb = g_xT + (size_t)b * NPIX * CIN;
    const __half* wb  = (NTAPS == 9) ? g_wvh : g_wkh;

    int lch = tid & 15;
    int ay[4], ax[4];
#pragma unroll
    for (int i = 0; i < 4; i++) {
        int row = (tid >> 4) + i * 16;
        int p = m0 + row;
        ay[i] = p / IMGW;
        ax[i] = p - ay[i] * IMGW;
    }

    const int NS = NTAPS * 2;
    auto load_stage = [&](int s, int buf) {
        int tap = (NTAPS == 9) ? (s >> 1) : 0;
        int kc  = s & 1;
        int dy = (NTAPS == 9) ? (tap / 3 - 1) : 0;
        int dx = (NTAPS == 9) ? (tap % 3 - 1) : 0;
        int off = dy * IMGW + dx;
        uint32_t ab = AB0 + buf * 16384, bb = BB0 + buf * 16384;
#pragma unroll
        for (int i = 0; i < 4; i++) {
            int row = (tid >> 4) + i * 16;
            bool valid = (NTAPS == 1) ||
                         (((unsigned)(ay[i] + dy) < (unsigned)IMGW) &&
                          ((unsigned)(ax[i] + dx) < (unsigned)IMGW));
            int srow = m0 + row + (valid ? off : 0);
            cpa16(ab + row * 256 + ((lch ^ (row & 7)) << 4),
                  xTb + (size_t)srow * CIN + kc * 128 + lch * 8, valid ? 16 : 0);
        }
#pragma unroll
        for (int i = 0; i < 4; i++) {            // B: 64 rows x 16 chunks
            int idx = tid + i * 256;
            int row = idx >> 4, ch = idx & 15;
            cpa16(bb + row * 256 + ((ch ^ (row & 7)) << 4),
                  wb + (size_t)(tap * COUT + c0 + row) * CIN + kc * 128 + ch * 8, 16);
        }
        CP_COMMIT();
    };

    float acc[4][4] = {};
    int arow  = wm * 16 + (lane & 15);
    int achp  = (lane >> 4);
    int bchp  = ((lane >> 3) & 1);
    int brow0 = (lane & 7) + ((lane >> 4) << 3);

    load_stage(0, 0);
    for (int s = 0; s < NS; s++) {
        if (s + 1 < NS) { load_stage(s + 1, (s + 1) & 1); CP_WAIT(1); }
        else            { CP_WAIT(0); }
        __syncthreads();
        uint32_t ab = AB0 + (s & 1) * 16384, bb = BB0 + (s & 1) * 16384;

        uint32_t afr[2][4], bfr[2][2][4];
        {
            int ch = achp;
            ldsm4(afr[0], ab + arow * 256 + ((ch ^ (arow & 7)) << 4));
#pragma unroll
            for (int np = 0; np < 2; np++) {
                int row = wn * 32 + np * 16 + brow0;
                ldsm4(bfr[0][np], bb + row * 256 + ((bchp ^ (row & 7)) << 4));
            }
        }
#pragma unroll
        for (int k16 = 0; k16 < 8; k16++) {
            int cur = k16 & 1, nx = cur ^ 1;
            if (k16 < 7) {
                int ch = (k16 + 1) * 2 + achp;
                ldsm4(afr[nx], ab + arow * 256 + ((ch ^ (arow & 7)) << 4));
#pragma unroll
                for (int np = 0; np < 2; np++) {
                    int row = wn * 32 + np * 16 + brow0;
                    int chb = (k16 + 1) * 2 + bchp;
                    ldsm4(bfr[nx][np], bb + row * 256 + ((chb ^ (row & 7)) << 4));
                }
            }
#pragma unroll
            for (int np = 0; np < 2; np++) {
                mma_f16(acc[2 * np],     afr[cur], bfr[cur][np][0], bfr[cur][np][1]);
                mma_f16(acc[2 * np + 1], afr[cur], bfr[cur][np][2], bfr[cur][np][3]);
            }
        }
        __syncthreads();
    }
    // epilogue: K scaled by sqrt(log2e) so S is natively in log2 domain
    int r0 = m0 + wm * 16 + (lane >> 2);
#pragma unroll
    for (int half = 0; half < 2; half++) {
        int rr = r0 + half * 8;
#pragma unroll
        for (int nt = 0; nt < 4; nt++) {
            int col = wn * 32 + nt * 8 + (lane & 3) * 2;
            float b0 = (NTAPS == 9) ? bias_v[c0 + col]     : g_kbias[c0 + col];
            float b1 = (NTAPS == 9) ? bias_v[c0 + col + 1] : g_kbias[c0 + col + 1];
            float v0 = acc[nt][half * 2] + b0;
            float v1 = acc[nt][half * 2 + 1] + b1;
            if (NTAPS == 1) {
                __half2 h = __floats2half2_rn(v0 * SQRT_LOG2E, v1 * SQRT_LOG2E);
                *(uint32_t*)(g_Kh + ((size_t)b * NPIX + rr) * COUT + c0 + col) = *(uint32_t*)&h;
            } else {
                __nv_bfloat162 h = __floats2bfloat162_rn(v0, v1);
                *(uint32_t*)(g_V + ((size_t)b * NPIX + rr) * COUT + c0 + col) = *(uint32_t*)&h;
            }
        }
    }
}

// ---------------- warp-specialized flash attention (444 uneven jobs) --------------
#define BFULL0 1
#define BEMPTY0 3
#define BSLOC 5
#define BPVLOC 6
__global__ __launch_bounds__(384) void flash_kernel() {
    extern __shared__ unsigned char smem[];
    const uint32_t sb = smem_u32(smem);
    const uint32_t KB0 = sb;                       // 2 x 32768
    const uint32_t VB0 = sb + 65536;               // 2 x 65536
    const uint32_t PB0 = sb + 65536 + 131072;      // 2 x 16384

    int tid = threadIdx.x, lane = tid & 31, wid = tid >> 5;

    // decode job: big jobs first (work-steal fills tail with small jobs)
    int bid = blockIdx.x;
    int qjob, split, kbase, nit;
    if (bid < NBIG) {
        qjob = bid >> 1; split = bid & 1;
        kbase = split * 3200; nit = 25;
    } else {
        int t = bid - NBIG;
        qjob = QSPLIT2 + t / 3; split = t % 3;
        kbase = split * 2176; nit = (split < 2) ? 17 : 16;
    }
    int b = qjob / 100, q0 = (qjob % 100) * QT;

    const __half* Kb = g_Kh + (size_t)b * NPIX * CK;
    const __nv_bfloat16* Vb = g_V + (size_t)b * NPIX * CV;

    if (wid < 4) {
        // ================= S-group (128 threads) =================
#pragma unroll
        for (int i = 0; i < 8; i++) {
            int idx = tid + i * 128;
            int row = idx >> 4, ch = idx & 15;
            cpa16(PB0 + row * 256 + ((ch ^ (row & 7)) << 4),
                  Kb + (size_t)(q0 + row) * CK + ch * 8, 16);
        }
        CP_COMMIT();
#pragma unroll
        for (int i = 0; i < 16; i++) {
            int idx = tid + i * 128;
            int row = idx >> 4, ch = idx & 15;
            cpa16(KB0 + row * 256 + ((ch ^ (row & 7)) << 4),
                  Kb + (size_t)(kbase + row) * CK + ch * 8, 16);
        }
        CP_COMMIT();
        CP_WAIT(1);
        bar_sync(BSLOC, 128);

        uint32_t aq[8][4];
        {
            int row = wid * 16 + (lane & 15);
#pragma unroll
            for (int k16 = 0; k16 < 8; k16++) {
                int ch = k16 * 2 + (lane >> 4);
                ldsm4(aq[k16], PB0 + row * 256 + ((ch ^ (row & 7)) << 4));
            }
        }

        int srow0 = (lane & 7) + ((lane >> 4) << 3);
        int schp  = ((lane >> 3) & 1);
        float ps0 = 0.f, ps1 = 0.f;
        for (int it = 0; it < nit; it++) {
            int buf = it & 1;
            if (it + 1 < nit) {
                bar_sync(BSLOC, 128);
#pragma unroll
                for (int i = 0; i < 16; i++) {
                    int idx = tid + i * 128;
                    int row = idx >> 4, ch = idx & 15;
                    cpa16(KB0 + (buf ^ 1) * 32768 + row * 256 + ((ch ^ (row & 7)) << 4),
                          Kb + (size_t)(kbase + (it + 1) * KT + row) * CK + ch * 8, 16);
                }
                CP_COMMIT();
                CP_WAIT(1);
            } else {
                CP_WAIT(0);
            }
            bar_sync(BSLOC, 128);

            uint32_t kb = KB0 + buf * 32768;
            float sacc[16][4] = {};
            uint32_t bqf[2][4];
            {
                ldsm4(bqf[0], kb + srow0 * 256 + ((schp ^ (srow0 & 7)) << 4));
            }
#pragma unroll
            for (int idx = 0; idx < 64; idx++) {
                int k16 = idx >> 3, np = idx & 7;
                int cur = idx & 1, nx = cur ^ 1;
                if (idx < 63) {
                    int k16n = (idx + 1) >> 3, npn = (idx + 1) & 7;
                    int row = npn * 16 + srow0;
                    int ch  = k16n * 2 + schp;
                    ldsm4(bqf[nx], kb + row * 256 + ((ch ^ (row & 7)) << 4));
                }
                mma_f16(sacc[2 * np],     aq[k16], bqf[cur][0], bqf[cur][1]);
                mma_f16(sacc[2 * np + 1], aq[k16], bqf[cur][2], bqf[cur][3]);
            }

            if (it >= 2) bar_sync(BEMPTY0 + buf, 384);   // PV consumed P buf (it-2)

            uint32_t pb = PB0 + buf * 16384;
            int prow0 = wid * 16 + (lane >> 2), prow1 = prow0 + 8;
            int cb = (lane & 3) * 4;
#pragma unroll
            for (int f = 0; f < 16; f++) {
                float* s = sacc[f];
                float e0 = ex2(s[0]), e1 = ex2(s[1]);
                float e2 = ex2(s[2]), e3 = ex2(s[3]);
                ps0 += e0 + e1;
                ps1 += e2 + e3;
                __nv_bfloat162 h0 = __floats2bfloat162_rn(e0, e1);
                __nv_bfloat162 h1 = __floats2bfloat162_rn(e2, e3);
                *(uint32_t*)(smem + (pb - sb) + prow0 * 256 + ((f ^ (prow0 & 7)) << 4) + cb) = *(uint32_t*)&h0;
                *(uint32_t*)(smem + (pb - sb) + prow1 * 256 + ((f ^ (prow1 & 7)) << 4) + cb) = *(uint32_t*)&h1;
            }
            bar_arrive(BFULL0 + buf, 384);
        }
        bar_sync(BEMPTY0 + ((nit - 2) & 1), 384);
        bar_sync(BEMPTY0 + ((nit - 1) & 1), 384);

        ps0 += __shfl_xor_sync(0xffffffff, ps0, 1);
        ps0 += __shfl_xor_sync(0xffffffff, ps0, 2);
        ps1 += __shfl_xor_sync(0xffffffff, ps1, 1);
        ps1 += __shfl_xor_sync(0xffffffff, ps1, 2);
        if ((lane & 3) == 0) {
            int base = (b * 3 + split) * NPIX + q0 + wid * 16 + (lane >> 2);
            g_l[base]     = ps0;
            g_l[base + 8] = ps1;
        }
    } else {
        // ================= PV-group (256 threads) =================
        int pvtid = tid - 128;
        int pvid = wid - 4;
        int pm = pvid & 1, pc = pvid >> 1;

        auto load_v = [&](int it, int buf) {
#pragma unroll
            for (int i = 0; i < 16; i++) {
                int idx = pvtid + i * 256;
                int row = idx >> 5, ch = idx & 31;
                cpa16(VB0 + buf * 65536 + row * 512 + ((ch ^ (row & 7)) << 4),
                      Vb + (size_t)(kbase + it * KT + row) * CV + ch * 8, 16);
            }
            CP_COMMIT();
        };

        float acc[2][8][4] = {};
        int prowb = pm * 32 + (lane & 15);
        int krow0 = (lane & 7) + ((lane >> 3) & 1) * 8;
        int nchp  = pc * 8 + (lane >> 4);
        int achp  = (lane >> 4);

        load_v(0, 0);
        for (int it = 0; it < nit; it++) {
            int buf = it & 1;
            if (it + 1 < nit) {
                bar_sync(BPVLOC, 256);
                load_v(it + 1, buf ^ 1);
                CP_WAIT(1);
            } else {
                CP_WAIT(0);
            }
            bar_sync(BPVLOC, 256);
            bar_sync(BFULL0 + buf, 384);

            uint32_t pb = PB0 + buf * 16384, vb = VB0 + buf * 65536;
            uint32_t apf[2][2][4], bqf[2][4];
            {
                ldsm4(apf[0][0], pb + prowb * 256 + ((achp ^ (prowb & 7)) << 4));
                ldsm4(apf[0][1], pb + (prowb + 16) * 256 + ((achp ^ ((prowb + 16) & 7)) << 4));
                ldsm4t(bqf[0], vb + krow0 * 512 + ((nchp ^ (krow0 & 7)) << 4));
            }
#pragma unroll
            for (int idx = 0; idx < 32; idx++) {
                int k16 = idx >> 2, np = idx & 3;
                int cur = idx & 1, nx = cur ^ 1;
                int kc = k16 & 1, kn = kc ^ 1;
                if (np == 0 && k16 < 7) {
                    int ch = (k16 + 1) * 2 + achp;
                    ldsm4(apf[kn][0], pb + prowb * 256 + ((ch ^ (prowb & 7)) << 4));
                    ldsm4(apf[kn][1], pb + (prowb + 16) * 256 + ((ch ^ ((prowb + 16) & 7)) << 4));
                }
                if (idx < 31) {
                    int k16n = (idx + 1) >> 2, npn = (idx + 1) & 3;
                    int krow = k16n * 16 + krow0;
                    int nch  = npn * 2 + nchp;
                    ldsm4t(bqf[nx], vb + krow * 512 + ((nch ^ (krow & 7)) << 4));
                }
                mma_bf16(acc[0][2 * np],     apf[kc][0], bqf[cur][0], bqf[cur][1]);
                mma_bf16(acc[0][2 * np + 1], apf[kc][0], bqf[cur][2], bqf[cur][3]);
                mma_bf16(acc[1][2 * np],     apf[kc][1], bqf[cur][0], bqf[cur][1]);
                mma_bf16(acc[1][2 * np + 1], apf[kc][1], bqf[cur][2], bqf[cur][3]);
            }
            bar_arrive(BEMPTY0 + buf, 384);
        }

        float* op = g_part + ((size_t)(b * 3 + split) * NPIX + q0) * CV;
#pragma unroll
        for (int mt = 0; mt < 2; mt++) {
            int r = pm * 32 + mt * 16 + (lane >> 2);
#pragma unroll
            for (int n8 = 0; n8 < 8; n8++) {
                int col = pc * 64 + n8 * 8 + (lane & 3) * 2;
                *(float2*)(op + (size_t)r * CV + col)       = make_float2(acc[mt][n8][0], acc[mt][n8][1]);
                *(float2*)(op + (size_t)(r + 8) * CV + col) = make_float2(acc[mt][n8][2], acc[mt][n8][3]);
            }
        }
    }
}

// ---------------- out = ww @ (sum(part_i)/l)^T + bw + x  (fused combine) ----------
__global__ __launch_bounds__(256) void gemm_out_kernel(const float* __restrict__ bw,
                                                       const float* __restrict__ x,
                                                       float* __restrict__ out) {
    extern __shared__ unsigned char smem[];
    uint32_t sb = smem_u32(smem);
    const uint32_t SA = sb, SB = sb + 65536;
    float* sinv = (float*)(smem + 131072);   // [128]

    int tid = threadIdx.x, lane = tid & 31, wid = tid >> 5;
    int wm = wid & 3, wn = wid >> 2;
    int b = blockIdx.z, co0 = blockIdx.y * 128, n0 = blockIdx.x * 128;

    // A: ww via cp.async
#pragma unroll
    for (int i = 0; i < 16; i++) {
        int idx = tid + i * 256;
        int row = idx >> 5, ch = idx & 31;
        cpa16(SA + row * 512 + ((ch ^ (row & 7)) << 4),
              g_wwh + (size_t)(co0 + row) * CV + ch * 8, 16);
    }
    CP_COMMIT();

    // per-row split count + 1/sum(l_i)
    int qt0 = n0 / 64;   // qtile within batch for rows [0,64)
    if (tid < 128) {
        int qjob = b * 100 + qt0 + (tid >> 6);
        float l = g_l[(b * 3 + 0) * NPIX + n0 + tid] + g_l[(b * 3 + 1) * NPIX + n0 + tid];
        if (qjob >= QSPLIT2) l += g_l[(b * 3 + 2) * NPIX + n0 + tid];
        sinv[tid] = 1.0f / l;
    }
    __syncthreads();

    // B: ctx tile from partials, normalized, fp16 swizzled
    const float* p0 = g_part + ((size_t)(b * 3 + 0) * NPIX + n0) * CV;
    const float* p1 = g_part + ((size_t)(b * 3 + 1) * NPIX + n0) * CV;
    const float* p2 = g_part + ((size_t)(b * 3 + 2) * NPIX + n0) * CV;
#pragma unroll
    for (int i = 0; i < 16; i++) {
        int idx = tid + i * 256;
        int row = idx >> 5, ch = idx & 31;
        float inv = sinv[row];
        bool three = (b * 100 + qt0 + (row >> 6)) >= QSPLIT2;
        const float* a0 = p0 + (size_t)row * CV + ch * 8;
        const float* a1 = p1 + (size_t)row * CV + ch * 8;
        float4 u0 = *(const float4*)a0,       v0 = *(const float4*)a1;
        float4 u1 = *(const float4*)(a0 + 4), v1 = *(const float4*)(a1 + 4);
        float s0x = u0.x + v0.x, s0y = u0.y + v0.y, s0z = u0.z + v0.z, s0w = u0.w + v0.w;
        float s1x = u1.x + v1.x, s1y = u1.y + v1.y, s1z = u1.z + v1.z, s1w = u1.w + v1.w;
        if (three) {
            const float* a2 = p2 + (size_t)row * CV + ch * 8;
            float4 w0 = *(const float4*)a2, w1 = *(const float4*)(a2 + 4);
            s0x += w0.x; s0y += w0.y; s0z += w0.z; s0w += w0.w;
            s1x += w1.x; s1y += w1.y; s1z += w1.z; s1w += w1.w;
        }
        __half2 h0 = __floats2half2_rn(s0x * inv, s0y * inv);
        __half2 h1 = __floats2half2_rn(s0z * inv, s0w * inv);
        __half2 h2 = __floats2half2_rn(s1x * inv, s1y * inv);
        __half2 h3 = __floats2half2_rn(s1z * inv, s1w * inv);
        uint4 pk;
        pk.x = *(uint32_t*)&h0; pk.y = *(uint32_t*)&h1;
        pk.z = *(uint32_t*)&h2; pk.w = *(uint32_t*)&h3;
        *(uint4*)(smem + (SB - sb) + row * 512 + ((ch ^ (row & 7)) << 4)) = pk;
    }
    CP_WAIT(0);
    __syncthreads();

    float acc[2][8][4] = {};
#pragma unroll
    for (int k16 = 0; k16 < 16; k16++) {
        uint32_t a[2][4];
#pragma unroll
        for (int mt = 0; mt < 2; mt++) {
            int row = wm * 32 + mt * 16 + (lane & 15);
            int ch  = k16 * 2 + (lane >> 4);
            ldsm4(a[mt], SA + row * 512 + ((ch ^ (row & 7)) << 4));
        }
        uint32_t bq[4][4];
#pragma unroll
        for (int np = 0; np < 4; np++) {
            int row = wn * 64 + np * 16 + (lane & 7) + ((lane >> 4) << 3);
            int ch  = k16 * 2 + ((lane >> 3) & 1);
            ldsm4(bq[np], SB + row * 512 + ((ch ^ (row & 7)) << 4));
        }
#pragma unroll
        for (int mt = 0; mt < 2; mt++)
#pragma unroll
            for (int np = 0; np < 4; np++) {
                mma_f16(acc[mt][2 * np],     a[mt], bq[np][0], bq[np][1]);
                mma_f16(acc[mt][2 * np + 1], a[mt], bq[np][2], bq[np][3]);
            }
    }
#pragma unroll
    for (int mt = 0; mt < 2; mt++) {
#pragma unroll
        for (int half = 0; half < 2; half++) {
            int co = co0 + wm * 32 + mt * 16 + (lane >> 2) + half * 8;
            float bwv = bw[co];
            size_t xb = ((size_t)b * CIN + co) * NPIX + n0;
            size_t ob = ((size_t)b * CV  + co) * NPIX + n0;
#pragma unroll
            for (int n8 = 0; n8 < 8; n8++) {
                int col = wn * 64 + n8 * 8 + (lane & 3) * 2;
                float2 xv = *(const float2*)(x + xb + col);
                float2 o;
                o.x = acc[mt][n8][half * 2]     + bwv + xv.x;
                o.y = acc[mt][n8][half * 2 + 1] + bwv + xv.y;
                *(float2*)(out + ob + col) = o;
            }
        }
    }
}

// ---------------- launch ----------------------------------------------------------
extern "C" void kernel_launch(void* const* d_in, const int* in_sizes, int n_in,
                              void* d_out, int out_size) {
    (void)in_sizes; (void)n_in; (void)out_size;
    const float* x     = (const float*)d_in[0];
    const float* wk    = (const float*)d_in[1];
    const float* bk    = (const float*)d_in[2];
    const float* gamma = (const float*)d_in[3];
    const float* beta  = (const float*)d_in[4];
    const float* rmean = (const float*)d_in[5];
    const float* rvar  = (const float*)d_in[6];
    const float* wv    = (const float*)d_in[7];
    const float* bv    = (const float*)d_in[8];
    const float* ww    = (const float*)d_in[9];
    const float* bw    = (const float*)d_in[10];
    float* out = (float*)d_out;

    const int CONV_SMEM = 65536;
    const int OUT_SMEM = 131072 + 1024;
    const int FLASH_SMEM = 65536 + 131072 + 32768;     // 229376
    cudaFuncSetAttribute(conv_mma_kernel<CK, 1>, cudaFuncAttributeMaxDynamicSharedMemorySize, CONV_SMEM);
    cudaFuncSetAttribute(conv_mma_kernel<CV, 9>, cudaFuncAttributeMaxDynamicSharedMemorySize, CONV_SMEM);
    cudaFuncSetAttribute(flash_kernel, cudaFuncAttributeMaxDynamicSharedMemorySize, FLASH_SMEM);
    cudaFuncSetAttribute(gemm_out_kernel, cudaFuncAttributeMaxDynamicSharedMemorySize, OUT_SMEM);

    transpose_prep_kernel<<<dim3(NPIX / 32, CIN / 32, 2), 256>>>(x, wk, bk, gamma, beta,
                                                                 rmean, rvar, wv, ww);
    conv_mma_kernel<CK, 1><<<dim3(CK / 64, NPIX / 64, 2), 256, CONV_SMEM>>>(bv);
    conv_mma_kernel<CV, 9><<<dim3(CV / 64, NPIX / 64, 2), 256, CONV_SMEM>>>(bv);
    flash_kernel<<<444, 384, FLASH_SMEM>>>();
    gemm_out_kernel<<<dim3(NPIX / 128, CV / 128, 2), 256, OUT_SMEM>>>(bw, x, out);
}

// round 17
// speedup vs baseline: 1.0470x; 1.0470x over previous
#include <cuda_runtime.h>
#include <cuda_bf16.h>
#include <cuda_fp16.h>
#include <stdint.h>

#define NPIX 6400
#define IMGW 80
#define CIN 256
#define CK 128
#define CV 256
#define QT 64
#define KT 128
#define SQRT_LOG2E 1.2011224087864498f
// job table: 156 q-jobs x 2 splits (25 it) + 44 q-jobs x 3 splits (17/17/16 it) = 444 CTAs
#define NBIG 312
#define QSPLIT2 156

// ---------------- scratch ----------------
__device__ __half g_xT[(size_t)2 * NPIX * CIN];
__device__ __half g_Kh[(size_t)2 * NPIX * CK];   // K pre-scaled by sqrt(log2e)
__device__ __nv_bfloat16 g_V[(size_t)2 * NPIX * CV];
__device__ float g_part[(size_t)2 * 3 * NPIX * CV];
__device__ float g_l[2 * 3 * NPIX];
__device__ float g_kbias[CK];
__device__ __half g_wkh[CK * CIN];
__device__ __half g_wvh[9 * CV * CIN];
__device__ __half g_wwh[CV * CV];

// ---------------- PTX helpers ----------------
__device__ __forceinline__ uint32_t smem_u32(const void* p) {
    uint32_t a;
    asm("{ .reg .u64 t; cvta.to.shared.u64 t, %1; cvt.u32.u64 %0, t; }" : "=r"(a) : "l"(p));
    return a;
}
__device__ __forceinline__ void ldsm4(uint32_t* r, uint32_t addr) {
    asm volatile("ldmatrix.sync.aligned.m8n8.x4.shared.b16 {%0,%1,%2,%3}, [%4];"
                 : "=r"(r[0]), "=r"(r[1]), "=r"(r[2]), "=r"(r[3]) : "r"(addr));
}
__device__ __forceinline__ void ldsm4t(uint32_t* r, uint32_t addr) {
    asm volatile("ldmatrix.sync.aligned.m8n8.x4.trans.shared.b16 {%0,%1,%2,%3}, [%4];"
                 : "=r"(r[0]), "=r"(r[1]), "=r"(r[2]), "=r"(r[3]) : "r"(addr));
}
__device__ __forceinline__ void mma_bf16(float* c, const uint32_t* a, uint32_t b0, uint32_t b1) {
    asm volatile("mma.sync.aligned.m16n8k16.row.col.f32.bf16.bf16.f32 "
                 "{%0,%1,%2,%3}, {%4,%5,%6,%7}, {%8,%9}, {%0,%1,%2,%3};"
                 : "+f"(c[0]), "+f"(c[1]), "+f"(c[2]), "+f"(c[3])
                 : "r"(a[0]), "r"(a[1]), "r"(a[2]), "r"(a[3]), "r"(b0), "r"(b1));
}
__device__ __forceinline__ void mma_f16(float* c, const uint32_t* a, uint32_t b0, uint32_t b1) {
    asm volatile("mma.sync.aligned.m16n8k16.row.col.f32.f16.f16.f32 "
                 "{%0,%1,%2,%3}, {%4,%5,%6,%7}, {%8,%9}, {%0,%1,%2,%3};"
                 : "+f"(c[0]), "+f"(c[1]), "+f"(c[2]), "+f"(c[3])
                 : "r"(a[0]), "r"(a[1]), "r"(a[2]), "r"(a[3]), "r"(b0), "r"(b1));
}
__device__ __forceinline__ void cpa16(uint32_t dst, const void* src, int sz) {
    asm volatile("cp.async.cg.shared.global [%0], [%1], 16, %2;"
                 :: "r"(dst), "l"(src), "r"(sz));
}
#define CP_COMMIT() asm volatile("cp.async.commit_group;" ::: "memory")
#define CP_WAIT(n)  asm volatile("cp.async.wait_group %0;" :: "n"(n) : "memory")
__device__ __forceinline__ void bar_sync(int id, int cnt) {
    asm volatile("bar.sync %0, %1;" :: "r"(id), "r"(cnt) : "memory");
}
__device__ __forceinline__ void bar_arrive(int id, int cnt) {
    asm volatile("bar.arrive %0, %1;" :: "r"(id), "r"(cnt) : "memory");
}
__device__ __forceinline__ float ex2(float x) {
    float y;
    asm("ex2.approx.ftz.f32 %0, %1;" : "=f"(y) : "f"(x));
    return y;
}

// ---------------- x transpose + weight prep (merged; one launch) ------------------
__global__ void transpose_prep_kernel(const float* __restrict__ x,
                                      const float* __restrict__ wk, const float* __restrict__ bk,
                                      const float* __restrict__ gamma, const float* __restrict__ beta,
                                      const float* __restrict__ rmean, const float* __restrict__ rvar,
                                      const float* __restrict__ wv, const float* __restrict__ ww) {
    __shared__ float t[32][33];
    int b = blockIdx.z, n0 = blockIdx.x * 32, c0 = blockIdx.y * 32;
    int tid = threadIdx.x, nl = tid & 31, cg = tid >> 5;

    // ---- prep (independent of the transpose data; interleaved for free) ----
    int flat = ((blockIdx.z * 8 + blockIdx.y) * 200 + blockIdx.x) * 256 + tid;
    if (flat < CK) {
        float inv = gamma[flat] * rsqrtf(rvar[flat] + 1e-5f);
        g_kbias[flat] = bk[flat] * inv + beta[flat] - rmean[flat] * inv;
    }
    if (flat < CK * CIN) {
        int c = flat / CIN;
        float inv = gamma[c] * rsqrtf(rvar[c] + 1e-5f);
        g_wkh[flat] = __float2half(wk[flat] * inv);
    }
    {
        int i2 = flat - CK * CIN;
        if (i2 >= 0 && i2 < CV * CV)
            g_wwh[i2] = __float2half(ww[i2]);
    }
    {
        int i3 = flat - (CK * CIN + CV * CV);
        if (i3 >= 0 && i3 < 9 * CV * CIN) {
            int tp = i3 / (CV * CIN);
            int rem = i3 - tp * CV * CIN;
            int o = rem / CIN;
            int i = rem - o * CIN;
            g_wvh[i3] = __float2half(wv[(o * CIN + i) * 9 + tp]);
        }
    }

    // ---- transpose ----
#pragma unroll
    for (int i = 0; i < 4; i++) {
        int c = cg + i * 8;
        t[c][nl] = x[((size_t)b * CIN + c0 + c) * NPIX + n0 + nl];
    }
    __syncthreads();
    __half2 h0 = __floats2half2_rn(t[cg * 4 + 0][nl], t[cg * 4 + 1][nl]);
    __half2 h1 = __floats2half2_rn(t[cg * 4 + 2][nl], t[cg * 4 + 3][nl]);
    uint2 v;
    v.x = *(uint32_t*)&h0; v.y = *(uint32_t*)&h1;
    *(uint2*)(g_xT + ((size_t)b * NPIX + n0 + nl) * CIN + c0 + cg * 4) = v;
}

// ---------------- conv as implicit NT GEMM (fp16 mma, BM=64, BN=128, BK=128) ------
template <int COUT, int NTAPS>
__global__ __launch_bounds__(256, 2) void conv_mma_kernel(const float* __restrict__ bias_v) {
    extern __shared__ unsigned char smem[];
    uint32_t sb = smem_u32(smem);
    const uint32_t AB0 = sb, BB0 = sb + 32768;   // A: 2x16KB, B: 2x32KB

    int tid = threadIdx.x, lane = tid & 31, wid = tid >> 5;
    int wm = wid & 3, wn = wid >> 2;
    int b = blockIdx.z, m0 = blockIdx.y * 64, c0 = blockIdx.x * 128;

    const __half* xTb = g_xT + (size_t)b * NPIX * CIN;
    const __half* wb  = (NTAPS == 9) ? g_wvh : g_wkh;

    int lch = tid & 15;
    int ay[4], ax[4];
#pragma unroll
    for (int i = 0; i < 4; i++) {
        int row = (tid >> 4) + i * 16;
        int p = m0 + row;
        ay[i] = p / IMGW;
        ax[i] = p - ay[i] * IMGW;
    }

    const int NS = NTAPS * 2;
    auto load_stage = [&](int s, int buf) {
        int tap = (NTAPS == 9) ? (s >> 1) : 0;
        int kc  = s & 1;
        int dy = (NTAPS == 9) ? (tap / 3 - 1) : 0;
        int dx = (NTAPS == 9) ? (tap % 3 - 1) : 0;
        int off = dy * IMGW + dx;
        uint32_t ab = AB0 + buf * 16384, bb = BB0 + buf * 32768;
#pragma unroll
        for (int i = 0; i < 4; i++) {
            int row = (tid >> 4) + i * 16;
            bool valid = (NTAPS == 1) ||
                         (((unsigned)(ay[i] + dy) < (unsigned)IMGW) &&
                          ((unsigned)(ax[i] + dx) < (unsigned)IMGW));
            int srow = m0 + row + (valid ? off : 0);
            cpa16(ab + row * 256 + ((lch ^ (row & 7)) << 4),
                  xTb + (size_t)srow * CIN + kc * 128 + lch * 8, valid ? 16 : 0);
        }
#pragma unroll
        for (int i = 0; i < 8; i++) {
            int idx = tid + i * 256;
            int row = idx >> 4, ch = idx & 15;
            cpa16(bb + row * 256 + ((ch ^ (row & 7)) << 4),
                  wb + (size_t)(tap * COUT + c0 + row) * CIN + kc * 128 + ch * 8, 16);
        }
        CP_COMMIT();
    };

    float acc[8][4] = {};
    int arow  = wm * 16 + (lane & 15);
    int achp  = (lane >> 4);
    int bchp  = ((lane >> 3) & 1);
    int brow0 = (lane & 7) + ((lane >> 4) << 3);

    load_stage(0, 0);
    for (int s = 0; s < NS; s++) {
        if (s + 1 < NS) { load_stage(s + 1, (s + 1) & 1); CP_WAIT(1); }
        else            { CP_WAIT(0); }
        __syncthreads();
        uint32_t ab = AB0 + (s & 1) * 16384, bb = BB0 + (s & 1) * 32768;

        uint32_t afr[2][4], bfr[2][4][4];
        {
            int ch = achp;
            ldsm4(afr[0], ab + arow * 256 + ((ch ^ (arow & 7)) << 4));
#pragma unroll
            for (int np = 0; np < 4; np++) {
                int row = wn * 64 + np * 16 + brow0;
                ldsm4(bfr[0][np], bb + row * 256 + ((bchp ^ (row & 7)) << 4));
            }
        }
#pragma unroll
        for (int k16 = 0; k16 < 8; k16++) {
            int cur = k16 & 1, nx = cur ^ 1;
            if (k16 < 7) {
                int ch = (k16 + 1) * 2 + achp;
                ldsm4(afr[nx], ab + arow * 256 + ((ch ^ (arow & 7)) << 4));
#pragma unroll
                for (int np = 0; np < 4; np++) {
                    int row = wn * 64 + np * 16 + brow0;
                    int chb = (k16 + 1) * 2 + bchp;
                    ldsm4(bfr[nx][np], bb + row * 256 + ((chb ^ (row & 7)) << 4));
                }
            }
#pragma unroll
            for (int np = 0; np < 4; np++) {
                mma_f16(acc[2 * np],     afr[cur], bfr[cur][np][0], bfr[cur][np][1]);
                mma_f16(acc[2 * np + 1], afr[cur], bfr[cur][np][2], bfr[cur][np][3]);
            }
        }
        __syncthreads();
    }
    // epilogue: K scaled by sqrt(log2e) so S is natively in log2 domain
    int r0 = m0 + wm * 16 + (lane >> 2);
#pragma unroll
    for (int half = 0; half < 2; half++) {
        int rr = r0 + half * 8;
#pragma unroll
        for (int nt = 0; nt < 8; nt++) {
            int col = wn * 64 + nt * 8 + (lane & 3) * 2;
            float b0 = (NTAPS == 9) ? bias_v[c0 + col]     : g_kbias[c0 + col];
            float b1 = (NTAPS == 9) ? bias_v[c0 + col + 1] : g_kbias[c0 + col + 1];
            float v0 = acc[nt][half * 2] + b0;
            float v1 = acc[nt][half * 2 + 1] + b1;
            if (NTAPS == 1) {
                __half2 h = __floats2half2_rn(v0 * SQRT_LOG2E, v1 * SQRT_LOG2E);
                *(uint32_t*)(g_Kh + ((size_t)b * NPIX + rr) * COUT + c0 + col) = *(uint32_t*)&h;
            } else {
                __nv_bfloat162 h = __floats2bfloat162_rn(v0, v1);
                *(uint32_t*)(g_V + ((size_t)b * NPIX + rr) * COUT + c0 + col) = *(uint32_t*)&h;
            }
        }
    }
}

// ---------------- warp-specialized flash attention (444 uneven jobs) --------------
#define BFULL0 1
#define BEMPTY0 3
#define BSLOC 5
#define BPVLOC 6
__global__ __launch_bounds__(384) void flash_kernel() {
    extern __shared__ unsigned char smem[];
    const uint32_t sb = smem_u32(smem);
    const uint32_t KB0 = sb;                       // 2 x 32768
    const uint32_t VB0 = sb + 65536;               // 2 x 65536
    const uint32_t PB0 = sb + 65536 + 131072;      // 2 x 16384

    int tid = threadIdx.x, lane = tid & 31, wid = tid >> 5;

    // decode job: big jobs first (work-steal fills tail with small jobs)
    int bid = blockIdx.x;
    int qjob, split, kbase, nit;
    if (bid < NBIG) {
        qjob = bid >> 1; split = bid & 1;
        kbase = split * 3200; nit = 25;
    } else {
        int t = bid - NBIG;
        qjob = QSPLIT2 + t / 3; split = t % 3;
        kbase = split * 2176; nit = (split < 2) ? 17 : 16;
    }
    int b = qjob / 100, q0 = (qjob % 100) * QT;

    const __half* Kb = g_Kh + (size_t)b * NPIX * CK;
    const __nv_bfloat16* Vb = g_V + (size_t)b * NPIX * CV;

    if (wid < 4) {
        // ================= S-group (128 threads) =================
#pragma unroll
        for (int i = 0; i < 8; i++) {
            int idx = tid + i * 128;
            int row = idx >> 4, ch = idx & 15;
            cpa16(PB0 + row * 256 + ((ch ^ (row & 7)) << 4),
                  Kb + (size_t)(q0 + row) * CK + ch * 8, 16);
        }
        CP_COMMIT();
#pragma unroll
        for (int i = 0; i < 16; i++) {
            int idx = tid + i * 128;
            int row = idx >> 4, ch = idx & 15;
            cpa16(KB0 + row * 256 + ((ch ^ (row & 7)) << 4),
                  Kb + (size_t)(kbase + row) * CK + ch * 8, 16);
        }
        CP_COMMIT();
        CP_WAIT(1);
        bar_sync(BSLOC, 128);

        uint32_t aq[8][4];
        {
            int row = wid * 16 + (lane & 15);
#pragma unroll
            for (int k16 = 0; k16 < 8; k16++) {
                int ch = k16 * 2 + (lane >> 4);
                ldsm4(aq[k16], PB0 + row * 256 + ((ch ^ (row & 7)) << 4));
            }
        }

        int srow0 = (lane & 7) + ((lane >> 4) << 3);
        int schp  = ((lane >> 3) & 1);
        float ps0 = 0.f, ps1 = 0.f;
        for (int it = 0; it < nit; it++) {
            int buf = it & 1;
            if (it + 1 < nit) {
                bar_sync(BSLOC, 128);
#pragma unroll
                for (int i = 0; i < 16; i++) {
                    int idx = tid + i * 128;
                    int row = idx >> 4, ch = idx & 15;
                    cpa16(KB0 + (buf ^ 1) * 32768 + row * 256 + ((ch ^ (row & 7)) << 4),
                          Kb + (size_t)(kbase + (it + 1) * KT + row) * CK + ch * 8, 16);
                }
                CP_COMMIT();
                CP_WAIT(1);
            } else {
                CP_WAIT(0);
            }
            bar_sync(BSLOC, 128);

            uint32_t kb = KB0 + buf * 32768;
            float sacc[16][4] = {};
            uint32_t bqf[2][4];
            {
                ldsm4(bqf[0], kb + srow0 * 256 + ((schp ^ (srow0 & 7)) << 4));
            }
#pragma unroll
            for (int idx = 0; idx < 64; idx++) {
                int k16 = idx >> 3, np = idx & 7;
                int cur = idx & 1, nx = cur ^ 1;
                if (idx < 63) {
                    int k16n = (idx + 1) >> 3, npn = (idx + 1) & 7;
                    int row = npn * 16 + srow0;
                    int ch  = k16n * 2 + schp;
                    ldsm4(bqf[nx], kb + row * 256 + ((ch ^ (row & 7)) << 4));
                }
                mma_f16(sacc[2 * np],     aq[k16], bqf[cur][0], bqf[cur][1]);
                mma_f16(sacc[2 * np + 1], aq[k16], bqf[cur][2], bqf[cur][3]);
            }

            if (it >= 2) bar_sync(BEMPTY0 + buf, 384);   // PV consumed P buf (it-2)

            uint32_t pb = PB0 + buf * 16384;
            int prow0 = wid * 16 + (lane >> 2), prow1 = prow0 + 8;
            int cb = (lane & 3) * 4;
#pragma unroll
            for (int f = 0; f < 16; f++) {
                float* s = sacc[f];
                float e0 = ex2(s[0]), e1 = ex2(s[1]);
                float e2 = ex2(s[2]), e3 = ex2(s[3]);
                ps0 += e0 + e1;
                ps1 += e2 + e3;
                __nv_bfloat162 h0 = __floats2bfloat162_rn(e0, e1);
                __nv_bfloat162 h1 = __floats2bfloat162_rn(e2, e3);
                *(uint32_t*)(smem + (pb - sb) + prow0 * 256 + ((f ^ (prow0 & 7)) << 4) + cb) = *(uint32_t*)&h0;
                *(uint32_t*)(smem + (pb - sb) + prow1 * 256 + ((f ^ (prow1 & 7)) << 4) + cb) = *(uint32_t*)&h1;
            }
            bar_arrive(BFULL0 + buf, 384);
        }
        bar_sync(BEMPTY0 + ((nit - 2) & 1), 384);
        bar_sync(BEMPTY0 + ((nit - 1) & 1), 384);

        ps0 += __shfl_xor_sync(0xffffffff, ps0, 1);
        ps0 += __shfl_xor_sync(0xffffffff, ps0, 2);
        ps1 += __shfl_xor_sync(0xffffffff, ps1, 1);
        ps1 += __shfl_xor_sync(0xffffffff, ps1, 2);
        if ((lane & 3) == 0) {
            int base = (b * 3 + split) * NPIX + q0 + wid * 16 + (lane >> 2);
            g_l[base]     = ps0;
            g_l[base + 8] = ps1;
        }
    } else {
        // ================= PV-group (256 threads) =================
        int pvtid = tid - 128;
        int pvid = wid - 4;
        int pm = pvid & 1, pc = pvid >> 1;

        auto load_v = [&](int it, int buf) {
#pragma unroll
            for (int i = 0; i < 16; i++) {
                int idx = pvtid + i * 256;
                int row = idx >> 5, ch = idx & 31;
                cpa16(VB0 + buf * 65536 + row * 512 + ((ch ^ (row & 7)) << 4),
                      Vb + (size_t)(kbase + it * KT + row) * CV + ch * 8, 16);
            }
            CP_COMMIT();
        };

        float acc[2][8][4] = {};
        int prowb = pm * 32 + (lane & 15);
        int krow0 = (lane & 7) + ((lane >> 3) & 1) * 8;
        int nchp  = pc * 8 + (lane >> 4);
        int achp  = (lane >> 4);

        load_v(0, 0);
        for (int it = 0; it < nit; it++) {
            int buf = it & 1;
            if (it + 1 < nit) {
                bar_sync(BPVLOC, 256);
                load_v(it + 1, buf ^ 1);
                CP_WAIT(1);
            } else {
                CP_WAIT(0);
            }
            bar_sync(BPVLOC, 256);
            bar_sync(BFULL0 + buf, 384);

            uint32_t pb = PB0 + buf * 16384, vb = VB0 + buf * 65536;
            uint32_t apf[2][2][4], bqf[2][4];
            {
                ldsm4(apf[0][0], pb + prowb * 256 + ((achp ^ (prowb & 7)) << 4));
                ldsm4(apf[0][1], pb + (prowb + 16) * 256 + ((achp ^ ((prowb + 16) & 7)) << 4));
                ldsm4t(bqf[0], vb + krow0 * 512 + ((nchp ^ (krow0 & 7)) << 4));
            }
#pragma unroll
            for (int idx = 0; idx < 32; idx++) {
                int k16 = idx >> 2, np = idx & 3;
                int cur = idx & 1, nx = cur ^ 1;
                int kc = k16 & 1, kn = kc ^ 1;
                if (np == 0 && k16 < 7) {
                    int ch = (k16 + 1) * 2 + achp;
                    ldsm4(apf[kn][0], pb + prowb * 256 + ((ch ^ (prowb & 7)) << 4));
                    ldsm4(apf[kn][1], pb + (prowb + 16) * 256 + ((ch ^ ((prowb + 16) & 7)) << 4));
                }
                if (idx < 31) {
                    int k16n = (idx + 1) >> 2, npn = (idx + 1) & 3;
                    int krow = k16n * 16 + krow0;
                    int nch  = npn * 2 + nchp;
                    ldsm4t(bqf[nx], vb + krow * 512 + ((nch ^ (krow & 7)) << 4));
                }
                mma_bf16(acc[0][2 * np],     apf[kc][0], bqf[cur][0], bqf[cur][1]);
                mma_bf16(acc[0][2 * np + 1], apf[kc][0], bqf[cur][2], bqf[cur][3]);
                mma_bf16(acc[1][2 * np],     apf[kc][1], bqf[cur][0], bqf[cur][1]);
                mma_bf16(acc[1][2 * np + 1], apf[kc][1], bqf[cur][2], bqf[cur][3]);
            }
            bar_arrive(BEMPTY0 + buf, 384);
        }

        float* op = g_part + ((size_t)(b * 3 + split) * NPIX + q0) * CV;
#pragma unroll
        for (int mt = 0; mt < 2; mt++) {
            int r = pm * 32 + mt * 16 + (lane >> 2);
#pragma unroll
            for (int n8 = 0; n8 < 8; n8++) {
                int col = pc * 64 + n8 * 8 + (lane & 3) * 2;
                *(float2*)(op + (size_t)r * CV + col)       = make_float2(acc[mt][n8][0], acc[mt][n8][1]);
                *(float2*)(op + (size_t)(r + 8) * CV + col) = make_float2(acc[mt][n8][2], acc[mt][n8][3]);
            }
        }
    }
}

// ---------------- out = ww @ (sum(part_i)/l)^T + bw + x  (fused combine) ----------
__global__ __launch_bounds__(256) void gemm_out_kernel(const float* __restrict__ bw,
                                                       const float* __restrict__ x,
                                                       float* __restrict__ out) {
    extern __shared__ unsigned char smem[];
    uint32_t sb = smem_u32(smem);
    const uint32_t SA = sb, SB = sb + 65536;
    float* sinv = (float*)(smem + 131072);   // [128]

    int tid = threadIdx.x, lane = tid & 31, wid = tid >> 5;
    int wm = wid & 3, wn = wid >> 2;
    int b = blockIdx.z, co0 = blockIdx.y * 128, n0 = blockIdx.x * 128;

    // A: ww via cp.async
#pragma unroll
    for (int i = 0; i < 16; i++) {
        int idx = tid + i * 256;
        int row = idx >> 5, ch = idx & 31;
        cpa16(SA + row * 512 + ((ch ^ (row & 7)) << 4),
              g_wwh + (size_t)(co0 + row) * CV + ch * 8, 16);
    }
    CP_COMMIT();

    // per-row split count + 1/sum(l_i)
    int qt0 = n0 / 64;   // qtile within batch for rows [0,64)
    if (tid < 128) {
        int qjob = b * 100 + qt0 + (tid >> 6);
        float l = g_l[(b * 3 + 0) * NPIX + n0 + tid] + g_l[(b * 3 + 1) * NPIX + n0 + tid];
        if (qjob >= QSPLIT2) l += g_l[(b * 3 + 2) * NPIX + n0 + tid];
        sinv[tid] = 1.0f / l;
    }
    __syncthreads();

    // B: ctx tile from partials, normalized, fp16 swizzled
    const float* p0 = g_part + ((size_t)(b * 3 + 0) * NPIX + n0) * CV;
    const float* p1 = g_part + ((size_t)(b * 3 + 1) * NPIX + n0) * CV;
    const float* p2 = g_part + ((size_t)(b * 3 + 2) * NPIX + n0) * CV;
#pragma unroll
    for (int i = 0; i < 16; i++) {
        int idx = tid + i * 256;
        int row = idx >> 5, ch = idx & 31;
        float inv = sinv[row];
        bool three = (b * 100 + qt0 + (row >> 6)) >= QSPLIT2;
        const float* a0 = p0 + (size_t)row * CV + ch * 8;
        const float* a1 = p1 + (size_t)row * CV + ch * 8;
        float4 u0 = *(const float4*)a0,       v0 = *(const float4*)a1;
        float4 u1 = *(const float4*)(a0 + 4), v1 = *(const float4*)(a1 + 4);
        float s0x = u0.x + v0.x, s0y = u0.y + v0.y, s0z = u0.z + v0.z, s0w = u0.w + v0.w;
        float s1x = u1.x + v1.x, s1y = u1.y + v1.y, s1z = u1.z + v1.z, s1w = u1.w + v1.w;
        if (three) {
            const float* a2 = p2 + (size_t)row * CV + ch * 8;
            float4 w0 = *(const float4*)a2, w1 = *(const float4*)(a2 + 4);
            s0x += w0.x; s0y += w0.y; s0z += w0.z; s0w += w0.w;
            s1x += w1.x; s1y += w1.y; s1z += w1.z; s1w += w1.w;
        }
        __half2 h0 = __floats2half2_rn(s0x * inv, s0y * inv);
        __half2 h1 = __floats2half2_rn(s0z * inv, s0w * inv);
        __half2 h2 = __floats2half2_rn(s1x * inv, s1y * inv);
        __half2 h3 = __floats2half2_rn(s1z * inv, s1w * inv);
        uint4 pk;
        pk.x = *(uint32_t*)&h0; pk.y = *(uint32_t*)&h1;
        pk.z = *(uint32_t*)&h2; pk.w = *(uint32_t*)&h3;
        *(uint4*)(smem + (SB - sb) + row * 512 + ((ch ^ (row & 7)) << 4)) = pk;
    }
    CP_WAIT(0);
    __syncthreads();

    float acc[2][8][4] = {};
#pragma unroll
    for (int k16 = 0; k16 < 16; k16++) {
        uint32_t a[2][4];
#pragma unroll
        for (int mt = 0; mt < 2; mt++) {
            int row = wm * 32 + mt * 16 + (lane & 15);
            int ch  = k16 * 2 + (lane >> 4);
            ldsm4(a[mt], SA + row * 512 + ((ch ^ (row & 7)) << 4));
        }
        uint32_t bq[4][4];
#pragma unroll
        for (int np = 0; np < 4; np++) {
            int row = wn * 64 + np * 16 + (lane & 7) + ((lane >> 4) << 3);
            int ch  = k16 * 2 + ((lane >> 3) & 1);
            ldsm4(bq[np], SB + row * 512 + ((ch ^ (row & 7)) << 4));
        }
#pragma unroll
        for (int mt = 0; mt < 2; mt++)
#pragma unroll
            for (int np = 0; np < 4; np++) {
                mma_f16(acc[mt][2 * np],     a[mt], bq[np][0], bq[np][1]);
                mma_f16(acc[mt][2 * np + 1], a[mt], bq[np][2], bq[np][3]);
            }
    }
#pragma unroll
    for (int mt = 0; mt < 2; mt++) {
#pragma unroll
        for (int half = 0; half < 2; half++) {
            int co = co0 + wm * 32 + mt * 16 + (lane >> 2) + half * 8;
            float bwv = bw[co];
            size_t xb = ((size_t)b * CIN + co) * NPIX + n0;
            size_t ob = ((size_t)b * CV  + co) * NPIX + n0;
#pragma unroll
            for (int n8 = 0; n8 < 8; n8++) {
                int col = wn * 64 + n8 * 8 + (lane & 3) * 2;
                float2 xv = *(const float2*)(x + xb + col);
                float2 o;
                o.x = acc[mt][n8][half * 2]     + bwv + xv.x;
                o.y = acc[mt][n8][half * 2 + 1] + bwv + xv.y;
                *(float2*)(out + ob + col) = o;
            }
        }
    }
}

// ---------------- launch ----------------------------------------------------------
extern "C" void kernel_launch(void* const* d_in, const int* in_sizes, int n_in,
                              void* d_out, int out_size) {
    (void)in_sizes; (void)n_in; (void)out_size;
    const float* x     = (const float*)d_in[0];
    const float* wk    = (const float*)d_in[1];
    const float* bk    = (const float*)d_in[2];
    const float* gamma = (const float*)d_in[3];
    const float* beta  = (const float*)d_in[4];
    const float* rmean = (const float*)d_in[5];
    const float* rvar  = (const float*)d_in[6];
    const float* wv    = (const float*)d_in[7];
    const float* bv    = (const float*)d_in[8];
    const float* ww    = (const float*)d_in[9];
    const float* bw    = (const float*)d_in[10];
    float* out = (float*)d_out;

    const int CONV_SMEM = 98304;
    const int OUT_SMEM = 131072 + 1024;
    const int FLASH_SMEM = 65536 + 131072 + 32768;     // 229376
    cudaFuncSetAttribute(conv_mma_kernel<CK, 1>, cudaFuncAttributeMaxDynamicSharedMemorySize, CONV_SMEM);
    cudaFuncSetAttribute(conv_mma_kernel<CV, 9>, cudaFuncAttributeMaxDynamicSharedMemorySize, CONV_SMEM);
    cudaFuncSetAttribute(flash_kernel, cudaFuncAttributeMaxDynamicSharedMemorySize, FLASH_SMEM);
    cudaFuncSetAttribute(gemm_out_kernel, cudaFuncAttributeMaxDynamicSharedMemorySize, OUT_SMEM);

    transpose_prep_kernel<<<dim3(NPIX / 32, CIN / 32, 2), 256>>>(x, wk, bk, gamma, beta,
                                                                 rmean, rvar, wv, ww);
    conv_mma_kernel<CK, 1><<<dim3(1, NPIX / 64, 2), 256, CONV_SMEM>>>(bv);
    conv_mma_kernel<CV, 9><<<dim3(CV / 128, NPIX / 64, 2), 256, CONV_SMEM>>>(bv);
    flash_kernel<<<444, 384, FLASH_SMEM>>>();
    gemm_out_kernel<<<dim3(NPIX / 128, CV / 128, 2), 256, OUT_SMEM>>>(bw, x, out);
}